// round 2
// baseline (speedup 1.0000x reference)
#include <cuda_runtime.h>
#include <math.h>

#define B 64
#define C 256
#define D 128
#define KTOP 8
#define G2 296
#define TILE 64
#define NCAND (G2*KTOP)
#define QS_LD 68
#define SIM_LD 65

// scratch (device globals: no allocations allowed)
__device__ float g_qhatT[D*B];            // q_hat transposed [d][b]
__device__ float g_cval[B*G2*KTOP];       // per-block top-8 values
__device__ int   g_cidx[B*G2*KTOP];       // per-block top-8 indices

__device__ __forceinline__ float warpsum(float v) {
    v += __shfl_xor_sync(0xffffffff, v, 16);
    v += __shfl_xor_sync(0xffffffff, v, 8);
    v += __shfl_xor_sync(0xffffffff, v, 4);
    v += __shfl_xor_sync(0xffffffff, v, 2);
    v += __shfl_xor_sync(0xffffffff, v, 1);
    return v;
}

// ---------------------------------------------------------------------------
// Kernel 1: q = query @ W_q^T + b_q, then L2-normalize; store transposed [d][b]
// ---------------------------------------------------------------------------
__global__ void qproj_kernel(const float* __restrict__ query,
                             const float* __restrict__ Wq,
                             const float* __restrict__ bq) {
    __shared__ float qrow[C];
    __shared__ float qp[D];
    __shared__ float red[4];
    __shared__ float s_inv;
    const int b = blockIdx.x;
    const int tid = threadIdx.x;          // 128 threads
    const int lane = tid & 31, w = tid >> 5;

    qrow[tid]       = query[b*C + tid];
    qrow[tid + 128] = query[b*C + tid + 128];
    __syncthreads();

    // each warp computes outputs d = w, w+4, ... with coalesced W_q reads
    for (int d = w; d < D; d += 4) {
        const float* wr = Wq + (size_t)d*C;
        float acc = 0.f;
        #pragma unroll
        for (int j = 0; j < 8; j++) {
            int c = lane + 32*j;
            acc += qrow[c] * wr[c];
        }
        acc = warpsum(acc);
        if (lane == 0) qp[d] = acc + bq[d];
    }
    __syncthreads();

    float v = qp[tid];
    float ss = warpsum(v*v);
    if (lane == 0) red[w] = ss;
    __syncthreads();
    if (tid == 0) {
        float s = red[0] + red[1] + red[2] + red[3];
        s_inv = 1.0f / fmaxf(sqrtf(s), 1e-12f);
    }
    __syncthreads();
    g_qhatT[tid*B + b] = qp[tid] * s_inv;
}

// ---------------------------------------------------------------------------
// Kernel 2: sim tile GEMM + per-block running top-8 per batch row
// smem: Qs[128][68] | Ks[128][68] | sims[64][65] | ssq4[256] | scale[64]
// ---------------------------------------------------------------------------
__global__ void sim_topk_kernel(const float* __restrict__ keys,
                                const float* __restrict__ importance,
                                int N) {
    extern __shared__ float smem2[];
    float* Qs    = smem2;
    float* Ks    = Qs + D*QS_LD;
    float* sims  = Ks + D*QS_LD;
    float* ssq4  = sims + B*SIM_LD;
    float* scale = ssq4 + 256;

    const int tid = threadIdx.x;          // 256 threads
    const int g   = blockIdx.x;

    // load resident Q (transposed) once
    for (int i = tid; i < D*B; i += 256) {
        int d = i >> 6, bb = i & 63;
        Qs[d*QS_LD + bb] = g_qhatT[i];
    }

    // running top-8 (threads 0..63 own one batch row each)
    float tv[KTOP]; int tix[KTOP];
    #pragma unroll
    for (int k = 0; k < KTOP; k++) { tv[k] = -INFINITY; tix[k] = 0; }
    float vmin = -INFINITY; int minpos = 0;

    const int T = (N + TILE - 1) / TILE;
    const int ty = tid >> 4, tx = tid & 15;       // 16x16 thread tile
    const int n_load = tid >> 2, j0 = tid & 3;    // 4 threads per key row

    for (int t = g; t < T; t += G2) {
        const int base = t * TILE;
        __syncthreads();   // Q ready (iter 0) / previous iteration fully done

        // --- load 64-key tile transposed into Ks[d][n] + partial sum-squares
        {
            int gk = base + n_load;
            bool valid = gk < N;
            const float4* krow = reinterpret_cast<const float4*>(keys + (size_t)gk * D);
            float local = 0.f;
            #pragma unroll
            for (int j = j0; j < 32; j += 4) {
                float4 v4 = valid ? krow[j] : make_float4(0.f,0.f,0.f,0.f);
                Ks[(4*j+0)*QS_LD + n_load] = v4.x;
                Ks[(4*j+1)*QS_LD + n_load] = v4.y;
                Ks[(4*j+2)*QS_LD + n_load] = v4.z;
                Ks[(4*j+3)*QS_LD + n_load] = v4.w;
                local += v4.x*v4.x + v4.y*v4.y + v4.z*v4.z + v4.w*v4.w;
            }
            ssq4[n_load*4 + j0] = local;   // deterministic (no float atomics)
        }
        __syncthreads();

        // --- per-key scale = importance / max(||k||, eps)
        if (tid < 64) {
            int gk = base + tid;
            float ss = ssq4[tid*4+0] + ssq4[tid*4+1] + ssq4[tid*4+2] + ssq4[tid*4+3];
            scale[tid] = (gk < N) ? importance[gk] / fmaxf(sqrtf(ss), 1e-12f) : 0.f;
        }
        __syncthreads();

        // --- 64x64 sim tile, 4x4 register blocking, float4 smem reads
        {
            float acc00=0,acc01=0,acc02=0,acc03=0;
            float acc10=0,acc11=0,acc12=0,acc13=0;
            float acc20=0,acc21=0,acc22=0,acc23=0;
            float acc30=0,acc31=0,acc32=0,acc33=0;
            const float* qb = Qs + 4*ty;
            const float* kb = Ks + 4*tx;
            #pragma unroll 4
            for (int d = 0; d < D; d++) {
                float4 qv = *reinterpret_cast<const float4*>(qb + d*QS_LD);
                float4 kv = *reinterpret_cast<const float4*>(kb + d*QS_LD);
                acc00 += qv.x*kv.x; acc01 += qv.x*kv.y; acc02 += qv.x*kv.z; acc03 += qv.x*kv.w;
                acc10 += qv.y*kv.x; acc11 += qv.y*kv.y; acc12 += qv.y*kv.z; acc13 += qv.y*kv.w;
                acc20 += qv.z*kv.x; acc21 += qv.z*kv.y; acc22 += qv.z*kv.z; acc23 += qv.z*kv.w;
                acc30 += qv.w*kv.x; acc31 += qv.w*kv.y; acc32 += qv.w*kv.z; acc33 += qv.w*kv.w;
            }
            float s0 = scale[4*tx+0], s1 = scale[4*tx+1], s2 = scale[4*tx+2], s3 = scale[4*tx+3];
            float* sr0 = sims + (4*ty+0)*SIM_LD + 4*tx;
            float* sr1 = sims + (4*ty+1)*SIM_LD + 4*tx;
            float* sr2 = sims + (4*ty+2)*SIM_LD + 4*tx;
            float* sr3 = sims + (4*ty+3)*SIM_LD + 4*tx;
            sr0[0]=acc00*s0; sr0[1]=acc01*s1; sr0[2]=acc02*s2; sr0[3]=acc03*s3;
            sr1[0]=acc10*s0; sr1[1]=acc11*s1; sr1[2]=acc12*s2; sr1[3]=acc13*s3;
            sr2[0]=acc20*s0; sr2[1]=acc21*s1; sr2[2]=acc22*s2; sr2[3]=acc23*s3;
            sr3[0]=acc30*s0; sr3[1]=acc31*s1; sr3[2]=acc32*s2; sr3[3]=acc33*s3;
        }
        __syncthreads();

        // --- update running top-8 (one thread per batch row)
        if (tid < 64) {
            const float* sr = sims + tid*SIM_LD;
            int nmax = (N - base < TILE) ? (N - base) : TILE;
            for (int n = 0; n < nmax; n++) {
                float v = sr[n];
                if (v > vmin) {
                    tv[minpos] = v; tix[minpos] = base + n;
                    vmin = tv[0]; minpos = 0;
                    #pragma unroll
                    for (int k = 1; k < KTOP; k++)
                        if (tv[k] < vmin) { vmin = tv[k]; minpos = k; }
                }
            }
        }
    }

    if (tid < 64) {
        int o = (tid*G2 + g)*KTOP;
        #pragma unroll
        for (int k = 0; k < KTOP; k++) { g_cval[o+k] = tv[k]; g_cidx[o+k] = tix[k]; }
    }
}

// ---------------------------------------------------------------------------
// Kernel 3: merge candidates -> global top-8, gather values, softmax attention,
// combine, out = mem @ W_comb^T + b_comb
// ---------------------------------------------------------------------------
__global__ void final_kernel(const float* __restrict__ values,
                             const float* __restrict__ w_attn,
                             const float* __restrict__ b_attn,
                             const float* __restrict__ Wcomb,
                             const float* __restrict__ bcomb,
                             float* __restrict__ out) {
    __shared__ float cv[NCAND];
    __shared__ int   ci[NCAND];
    __shared__ float rv[256];
    __shared__ int   rp[256];
    __shared__ int   topidx[KTOP];
    __shared__ float vs[KTOP*129];
    __shared__ float wa[D];
    __shared__ float ts[KTOP];
    __shared__ float sc[KTOP];
    __shared__ float ms[D];

    const int b = blockIdx.x;
    const int tid = threadIdx.x;          // 256 threads

    for (int i = tid; i < NCAND; i += 256) {
        cv[i] = g_cval[b*NCAND + i];
        ci[i] = g_cidx[b*NCAND + i];
    }
    if (tid < D) wa[tid] = w_attn[tid];
    __syncthreads();

    // 8 rounds of block argmax over candidates
    for (int k = 0; k < KTOP; k++) {
        float best = -INFINITY; int bp = 0;
        for (int i = tid; i < NCAND; i += 256)
            if (cv[i] > best) { best = cv[i]; bp = i; }
        rv[tid] = best; rp[tid] = bp;
        __syncthreads();
        for (int s = 128; s > 0; s >>= 1) {
            if (tid < s && rv[tid+s] > rv[tid]) { rv[tid] = rv[tid+s]; rp[tid] = rp[tid+s]; }
            __syncthreads();
        }
        if (tid == 0) { topidx[k] = ci[rp[0]]; cv[rp[0]] = -INFINITY; }
        __syncthreads();
    }

    // gather retrieved values
    if (tid < D) {
        #pragma unroll
        for (int k = 0; k < KTOP; k++)
            vs[k*129 + tid] = values[(size_t)topidx[k]*D + tid];
    }
    __syncthreads();

    // attention logits
    if (tid < KTOP) {
        float acc = b_attn[0];
        for (int d = 0; d < D; d++) acc += vs[tid*129 + d] * wa[d];
        ts[tid] = acc;
    }
    __syncthreads();
    if (tid == 0) {
        float m = ts[0];
        #pragma unroll
        for (int k = 1; k < KTOP; k++) m = fmaxf(m, ts[k]);
        float e[KTOP]; float s = 0.f;
        #pragma unroll
        for (int k = 0; k < KTOP; k++) { e[k] = expf(ts[k] - m); s += e[k]; }
        #pragma unroll
        for (int k = 0; k < KTOP; k++) sc[k] = e[k] / s;
    }
    __syncthreads();

    // weighted memory
    if (tid < D) {
        float m = 0.f;
        #pragma unroll
        for (int k = 0; k < KTOP; k++) m += sc[k] * vs[k*129 + tid];
        ms[tid] = m;
    }
    __syncthreads();

    // out = mem @ W_comb^T + b_comb  (warp-coalesced matvec)
    const int lane = tid & 31, w = tid >> 5;   // 8 warps
    for (int d = w; d < D; d += 8) {
        const float* wr = Wcomb + (size_t)d*D;
        float acc = 0.f;
        #pragma unroll
        for (int j = 0; j < 4; j++) {
            int e = lane + 32*j;
            acc += ms[e] * wr[e];
        }
        acc = warpsum(acc);
        if (lane == 0) out[b*D + d] = acc + bcomb[d];
    }
}

// ---------------------------------------------------------------------------
extern "C" void kernel_launch(void* const* d_in, const int* in_sizes, int n_in,
                              void* d_out, int out_size) {
    const float* query      = (const float*)d_in[0];
    const float* keys       = (const float*)d_in[1];
    const float* values     = (const float*)d_in[2];
    const float* importance = (const float*)d_in[3];
    const float* Wq         = (const float*)d_in[4];
    const float* bq         = (const float*)d_in[5];
    const float* w_attn     = (const float*)d_in[6];
    const float* b_attn     = (const float*)d_in[7];
    const float* Wcomb      = (const float*)d_in[8];
    const float* bcomb      = (const float*)d_in[9];
    const int N = in_sizes[1] / D;

    const size_t smem2_bytes = (size_t)(D*QS_LD*2 + B*SIM_LD + 256 + 64) * sizeof(float);
    cudaFuncSetAttribute(sim_topk_kernel,
                         cudaFuncAttributeMaxDynamicSharedMemorySize, (int)smem2_bytes);

    qproj_kernel<<<B, 128>>>(query, Wq, bq);
    sim_topk_kernel<<<G2, 256, smem2_bytes>>>(keys, importance, N);
    final_kernel<<<B, 256>>>(values, w_attn, b_attn, Wcomb, bcomb, (float*)d_out);
}

// round 3
// speedup vs baseline: 1.0005x; 1.0005x over previous
#include <cuda_runtime.h>
#include <math.h>

#define B 64
#define C 256
#define D 128
#define KTOP 8
#define G2 296
#define TILE 64
#define NCAND (G2*KTOP)
#define QS_LD 68
#define SIM_LD 65

// scratch (device globals: no allocations allowed)
__device__ float g_qhatT[D*B];            // q_hat transposed [d][b]
__device__ float g_cval[B*G2*KTOP];       // per-block top-8 values
__device__ int   g_cidx[B*G2*KTOP];       // per-block top-8 indices

__device__ __forceinline__ float warpsum(float v) {
    v += __shfl_xor_sync(0xffffffff, v, 16);
    v += __shfl_xor_sync(0xffffffff, v, 8);
    v += __shfl_xor_sync(0xffffffff, v, 4);
    v += __shfl_xor_sync(0xffffffff, v, 2);
    v += __shfl_xor_sync(0xffffffff, v, 1);
    return v;
}

// ---------------------------------------------------------------------------
// Kernel 1: q = query @ W_q^T + b_q, then L2-normalize; store transposed [d][b]
// ---------------------------------------------------------------------------
__global__ void qproj_kernel(const float* __restrict__ query,
                             const float* __restrict__ Wq,
                             const float* __restrict__ bq) {
    __shared__ float qrow[C];
    __shared__ float qp[D];
    __shared__ float red[4];
    __shared__ float s_inv;
    const int b = blockIdx.x;
    const int tid = threadIdx.x;          // 128 threads
    const int lane = tid & 31, w = tid >> 5;

    qrow[tid]       = query[b*C + tid];
    qrow[tid + 128] = query[b*C + tid + 128];
    __syncthreads();

    // each warp computes outputs d = w, w+4, ... with coalesced W_q reads
    for (int d = w; d < D; d += 4) {
        const float* wr = Wq + (size_t)d*C;
        float acc = 0.f;
        #pragma unroll
        for (int j = 0; j < 8; j++) {
            int c = lane + 32*j;
            acc += qrow[c] * wr[c];
        }
        acc = warpsum(acc);
        if (lane == 0) qp[d] = acc + bq[d];
    }
    __syncthreads();

    float v = qp[tid];
    float ss = warpsum(v*v);
    if (lane == 0) red[w] = ss;
    __syncthreads();
    if (tid == 0) {
        float s = red[0] + red[1] + red[2] + red[3];
        s_inv = 1.0f / fmaxf(sqrtf(s), 1e-12f);
    }
    __syncthreads();
    g_qhatT[tid*B + b] = qp[tid] * s_inv;
}

// ---------------------------------------------------------------------------
// Kernel 2: sim tile GEMM + per-block running top-8 per batch row
// smem: Qs[128][68] | Ks[128][68] | sims[64][65] | ssq4[256] | scale[64]
// ---------------------------------------------------------------------------
__global__ void sim_topk_kernel(const float* __restrict__ keys,
                                const float* __restrict__ importance,
                                int N) {
    extern __shared__ float smem2[];
    float* Qs    = smem2;
    float* Ks    = Qs + D*QS_LD;
    float* sims  = Ks + D*QS_LD;
    float* ssq4  = sims + B*SIM_LD;
    float* scale = ssq4 + 256;

    const int tid = threadIdx.x;          // 256 threads
    const int g   = blockIdx.x;

    // load resident Q (transposed) once
    for (int i = tid; i < D*B; i += 256) {
        int d = i >> 6, bb = i & 63;
        Qs[d*QS_LD + bb] = g_qhatT[i];
    }

    // running top-8 (threads 0..63 own one batch row each)
    float tv[KTOP]; int tix[KTOP];
    #pragma unroll
    for (int k = 0; k < KTOP; k++) { tv[k] = -INFINITY; tix[k] = 0; }
    float vmin = -INFINITY; int minpos = 0;

    const int T = (N + TILE - 1) / TILE;
    const int ty = tid >> 4, tx = tid & 15;       // 16x16 thread tile
    const int n_load = tid >> 2, j0 = tid & 3;    // 4 threads per key row

    for (int t = g; t < T; t += G2) {
        const int base = t * TILE;
        __syncthreads();   // Q ready (iter 0) / previous iteration fully done

        // --- load 64-key tile transposed into Ks[d][n] + partial sum-squares
        {
            int gk = base + n_load;
            bool valid = gk < N;
            const float4* krow = reinterpret_cast<const float4*>(keys + (size_t)gk * D);
            float local = 0.f;
            #pragma unroll
            for (int j = j0; j < 32; j += 4) {
                float4 v4 = valid ? krow[j] : make_float4(0.f,0.f,0.f,0.f);
                Ks[(4*j+0)*QS_LD + n_load] = v4.x;
                Ks[(4*j+1)*QS_LD + n_load] = v4.y;
                Ks[(4*j+2)*QS_LD + n_load] = v4.z;
                Ks[(4*j+3)*QS_LD + n_load] = v4.w;
                local += v4.x*v4.x + v4.y*v4.y + v4.z*v4.z + v4.w*v4.w;
            }
            ssq4[n_load*4 + j0] = local;   // deterministic (no float atomics)
        }
        __syncthreads();

        // --- per-key scale = importance / max(||k||, eps)
        if (tid < 64) {
            int gk = base + tid;
            float ss = ssq4[tid*4+0] + ssq4[tid*4+1] + ssq4[tid*4+2] + ssq4[tid*4+3];
            scale[tid] = (gk < N) ? importance[gk] / fmaxf(sqrtf(ss), 1e-12f) : 0.f;
        }
        __syncthreads();

        // --- 64x64 sim tile, 4x4 register blocking, float4 smem reads
        {
            float acc00=0,acc01=0,acc02=0,acc03=0;
            float acc10=0,acc11=0,acc12=0,acc13=0;
            float acc20=0,acc21=0,acc22=0,acc23=0;
            float acc30=0,acc31=0,acc32=0,acc33=0;
            const float* qb = Qs + 4*ty;
            const float* kb = Ks + 4*tx;
            #pragma unroll 4
            for (int d = 0; d < D; d++) {
                float4 qv = *reinterpret_cast<const float4*>(qb + d*QS_LD);
                float4 kv = *reinterpret_cast<const float4*>(kb + d*QS_LD);
                acc00 += qv.x*kv.x; acc01 += qv.x*kv.y; acc02 += qv.x*kv.z; acc03 += qv.x*kv.w;
                acc10 += qv.y*kv.x; acc11 += qv.y*kv.y; acc12 += qv.y*kv.z; acc13 += qv.y*kv.w;
                acc20 += qv.z*kv.x; acc21 += qv.z*kv.y; acc22 += qv.z*kv.z; acc23 += qv.z*kv.w;
                acc30 += qv.w*kv.x; acc31 += qv.w*kv.y; acc32 += qv.w*kv.z; acc33 += qv.w*kv.w;
            }
            float s0 = scale[4*tx+0], s1 = scale[4*tx+1], s2 = scale[4*tx+2], s3 = scale[4*tx+3];
            float* sr0 = sims + (4*ty+0)*SIM_LD + 4*tx;
            float* sr1 = sims + (4*ty+1)*SIM_LD + 4*tx;
            float* sr2 = sims + (4*ty+2)*SIM_LD + 4*tx;
            float* sr3 = sims + (4*ty+3)*SIM_LD + 4*tx;
            sr0[0]=acc00*s0; sr0[1]=acc01*s1; sr0[2]=acc02*s2; sr0[3]=acc03*s3;
            sr1[0]=acc10*s0; sr1[1]=acc11*s1; sr1[2]=acc12*s2; sr1[3]=acc13*s3;
            sr2[0]=acc20*s0; sr2[1]=acc21*s1; sr2[2]=acc22*s2; sr2[3]=acc23*s3;
            sr3[0]=acc30*s0; sr3[1]=acc31*s1; sr3[2]=acc32*s2; sr3[3]=acc33*s3;
        }
        __syncthreads();

        // --- update running top-8 (one thread per batch row)
        if (tid < 64) {
            const float* sr = sims + tid*SIM_LD;
            int nmax = (N - base < TILE) ? (N - base) : TILE;
            for (int n = 0; n < nmax; n++) {
                float v = sr[n];
                if (v > vmin) {
                    tv[minpos] = v; tix[minpos] = base + n;
                    vmin = tv[0]; minpos = 0;
                    #pragma unroll
                    for (int k = 1; k < KTOP; k++)
                        if (tv[k] < vmin) { vmin = tv[k]; minpos = k; }
                }
            }
        }
    }

    if (tid < 64) {
        int o = (tid*G2 + g)*KTOP;
        #pragma unroll
        for (int k = 0; k < KTOP; k++) { g_cval[o+k] = tv[k]; g_cidx[o+k] = tix[k]; }
    }
}

// ---------------------------------------------------------------------------
// Kernel 3: merge candidates -> global top-8, gather values, softmax attention,
// combine, out = mem @ W_comb^T + b_comb
// ---------------------------------------------------------------------------
__global__ void final_kernel(const float* __restrict__ values,
                             const float* __restrict__ w_attn,
                             const float* __restrict__ b_attn,
                             const float* __restrict__ Wcomb,
                             const float* __restrict__ bcomb,
                             float* __restrict__ out) {
    __shared__ float cv[NCAND];
    __shared__ int   ci[NCAND];
    __shared__ float rv[256];
    __shared__ int   rp[256];
    __shared__ int   topidx[KTOP];
    __shared__ float vs[KTOP*129];
    __shared__ float wa[D];
    __shared__ float ts[KTOP];
    __shared__ float sc[KTOP];
    __shared__ float ms[D];

    const int b = blockIdx.x;
    const int tid = threadIdx.x;          // 256 threads

    for (int i = tid; i < NCAND; i += 256) {
        cv[i] = g_cval[b*NCAND + i];
        ci[i] = g_cidx[b*NCAND + i];
    }
    if (tid < D) wa[tid] = w_attn[tid];
    __syncthreads();

    // 8 rounds of block argmax over candidates
    for (int k = 0; k < KTOP; k++) {
        float best = -INFINITY; int bp = 0;
        for (int i = tid; i < NCAND; i += 256)
            if (cv[i] > best) { best = cv[i]; bp = i; }
        rv[tid] = best; rp[tid] = bp;
        __syncthreads();
        for (int s = 128; s > 0; s >>= 1) {
            if (tid < s && rv[tid+s] > rv[tid]) { rv[tid] = rv[tid+s]; rp[tid] = rp[tid+s]; }
            __syncthreads();
        }
        if (tid == 0) { topidx[k] = ci[rp[0]]; cv[rp[0]] = -INFINITY; }
        __syncthreads();
    }

    // gather retrieved values
    if (tid < D) {
        #pragma unroll
        for (int k = 0; k < KTOP; k++)
            vs[k*129 + tid] = values[(size_t)topidx[k]*D + tid];
    }
    __syncthreads();

    // attention logits
    if (tid < KTOP) {
        float acc = b_attn[0];
        for (int d = 0; d < D; d++) acc += vs[tid*129 + d] * wa[d];
        ts[tid] = acc;
    }
    __syncthreads();
    if (tid == 0) {
        float m = ts[0];
        #pragma unroll
        for (int k = 1; k < KTOP; k++) m = fmaxf(m, ts[k]);
        float e[KTOP]; float s = 0.f;
        #pragma unroll
        for (int k = 0; k < KTOP; k++) { e[k] = expf(ts[k] - m); s += e[k]; }
        #pragma unroll
        for (int k = 0; k < KTOP; k++) sc[k] = e[k] / s;
    }
    __syncthreads();

    // weighted memory
    if (tid < D) {
        float m = 0.f;
        #pragma unroll
        for (int k = 0; k < KTOP; k++) m += sc[k] * vs[k*129 + tid];
        ms[tid] = m;
    }
    __syncthreads();

    // out = mem @ W_comb^T + b_comb  (warp-coalesced matvec)
    const int lane = tid & 31, w = tid >> 5;   // 8 warps
    for (int d = w; d < D; d += 8) {
        const float* wr = Wcomb + (size_t)d*D;
        float acc = 0.f;
        #pragma unroll
        for (int j = 0; j < 4; j++) {
            int e = lane + 32*j;
            acc += ms[e] * wr[e];
        }
        acc = warpsum(acc);
        if (lane == 0) out[b*D + d] = acc + bcomb[d];
    }
}

// ---------------------------------------------------------------------------
extern "C" void kernel_launch(void* const* d_in, const int* in_sizes, int n_in,
                              void* d_out, int out_size) {
    const float* query      = (const float*)d_in[0];
    const float* keys       = (const float*)d_in[1];
    const float* values     = (const float*)d_in[2];
    const float* importance = (const float*)d_in[3];
    const float* Wq         = (const float*)d_in[4];
    const float* bq         = (const float*)d_in[5];
    const float* w_attn     = (const float*)d_in[6];
    const float* b_attn     = (const float*)d_in[7];
    const float* Wcomb      = (const float*)d_in[8];
    const float* bcomb      = (const float*)d_in[9];
    const int N = in_sizes[1] / D;

    const size_t smem2_bytes = (size_t)(D*QS_LD*2 + B*SIM_LD + 256 + 64) * sizeof(float);
    cudaFuncSetAttribute(sim_topk_kernel,
                         cudaFuncAttributeMaxDynamicSharedMemorySize, (int)smem2_bytes);

    qproj_kernel<<<B, 128>>>(query, Wq, bq);
    sim_topk_kernel<<<G2, 256, smem2_bytes>>>(keys, importance, N);
    final_kernel<<<B, 256>>>(values, w_attn, b_attn, Wcomb, bcomb, (float*)d_out);
}

// round 4
// speedup vs baseline: 1.1624x; 1.1618x over previous
#include <cuda_runtime.h>
#include <math.h>

#define B 64
#define C 256
#define D 128
#define KTOP 8
#define G2 296
#define TILE 64
#define NCAND (G2*KTOP)
#define QS_LD 68
#define SIM_LD 65

// scratch (device globals: no allocations allowed)
__device__ float g_qT[D*B];               // q (unnormalized) transposed [d][b]
__device__ float g_cval[B*G2*KTOP];       // per-block top-8 values
__device__ int   g_cidx[B*G2*KTOP];       // per-block top-8 indices

__device__ __forceinline__ float warpsum(float v) {
    v += __shfl_xor_sync(0xffffffff, v, 16);
    v += __shfl_xor_sync(0xffffffff, v, 8);
    v += __shfl_xor_sync(0xffffffff, v, 4);
    v += __shfl_xor_sync(0xffffffff, v, 2);
    v += __shfl_xor_sync(0xffffffff, v, 1);
    return v;
}

// ---------------------------------------------------------------------------
// Kernel 1: q = query @ W_q^T + b_q  (NO normalization: 1/||q|| is a positive
// per-row scalar; top-k indices are invariant and sim values are selection-only)
// 2048 warps, each computes 4 outputs with interleaved reductions.
// ---------------------------------------------------------------------------
__global__ void qproj_kernel(const float* __restrict__ query,
                             const float* __restrict__ Wq,
                             const float* __restrict__ bq) {
    const int gw   = (blockIdx.x * blockDim.x + threadIdx.x) >> 5;  // 0..2047
    const int lane = threadIdx.x & 31;
    const int b    = gw >> 5;           // 0..63
    const int d0   = (gw & 31) * 4;     // 0,4,...,124

    const float* qr = query + (size_t)b * C;
    const float* w0 = Wq + (size_t)(d0 + 0) * C;
    const float* w1 = Wq + (size_t)(d0 + 1) * C;
    const float* w2 = Wq + (size_t)(d0 + 2) * C;
    const float* w3 = Wq + (size_t)(d0 + 3) * C;

    float a0 = 0.f, a1 = 0.f, a2 = 0.f, a3 = 0.f;
    #pragma unroll
    for (int j = 0; j < 8; j++) {
        int c = lane + 32 * j;
        float q = __ldg(qr + c);
        a0 += q * __ldg(w0 + c);
        a1 += q * __ldg(w1 + c);
        a2 += q * __ldg(w2 + c);
        a3 += q * __ldg(w3 + c);
    }
    #pragma unroll
    for (int off = 16; off; off >>= 1) {
        a0 += __shfl_xor_sync(0xffffffff, a0, off);
        a1 += __shfl_xor_sync(0xffffffff, a1, off);
        a2 += __shfl_xor_sync(0xffffffff, a2, off);
        a3 += __shfl_xor_sync(0xffffffff, a3, off);
    }
    if (lane == 0) {
        g_qT[(d0 + 0) * B + b] = a0 + bq[d0 + 0];
        g_qT[(d0 + 1) * B + b] = a1 + bq[d0 + 1];
        g_qT[(d0 + 2) * B + b] = a2 + bq[d0 + 2];
        g_qT[(d0 + 3) * B + b] = a3 + bq[d0 + 3];
    }
}

// ---------------------------------------------------------------------------
// Kernel 2: sim tile GEMM + per-block running top-8 per batch row.
// Software-pipelined: next tile prefetched into registers during compute/scan.
// smem: Qs[128][68] | Ks[128][68] | sims[64][65] | ssq4[256] | impS[64]
// ---------------------------------------------------------------------------
__global__ void __launch_bounds__(256, 2)
sim_topk_kernel(const float* __restrict__ keys,
                const float* __restrict__ importance,
                int N) {
    extern __shared__ float smem2[];
    float* Qs   = smem2;
    float* Ks   = Qs + D*QS_LD;
    float* sims = Ks + D*QS_LD;
    float* ssq4 = sims + B*SIM_LD;
    float* impS = ssq4 + 256;

    const int tid = threadIdx.x;          // 256 threads
    const int g   = blockIdx.x;

    // load resident Q (transposed) once
    for (int i = tid; i < D*B; i += 256) {
        int d = i >> 6, bb = i & 63;
        Qs[d*QS_LD + bb] = g_qT[i];
    }

    // running top-8 (threads 0..63 own one batch row each)
    float tv[KTOP]; int tix[KTOP];
    #pragma unroll
    for (int k = 0; k < KTOP; k++) { tv[k] = -INFINITY; tix[k] = 0; }
    float vmin = -INFINITY; int minpos = 0;

    const int T = (N + TILE - 1) / TILE;
    const int ty = tid >> 4, tx = tid & 15;       // 16x16 thread tile
    const int n_load = tid >> 2, j0 = tid & 3;    // 4 threads per key row

    // ---- prefetch helper state (registers)
    float4 pf[8];
    float  pimp = 0.f;

    auto do_prefetch = [&](int t) {
        int gk = t * TILE + n_load;
        bool valid = (t < T) && (gk < N);
        const float4* krow = reinterpret_cast<const float4*>(keys + (size_t)gk * D);
        #pragma unroll
        for (int jj = 0; jj < 8; jj++) {
            int j = j0 + 4*jj;
            pf[jj] = valid ? krow[j] : make_float4(0.f, 0.f, 0.f, 0.f);
        }
        if (j0 == 0) pimp = valid ? importance[gk] : 0.f;
    };

    do_prefetch(g);

    for (int t = g; t < T; t += G2) {
        const int base = t * TILE;
        __syncthreads();   // previous compute finished reading Ks / Qs loaded

        // --- store prefetched tile transposed into Ks[d][n] + partial sum-sq
        {
            float local = 0.f;
            #pragma unroll
            for (int jj = 0; jj < 8; jj++) {
                int j = j0 + 4*jj;
                float4 v4 = pf[jj];
                Ks[(4*j+0)*QS_LD + n_load] = v4.x;
                Ks[(4*j+1)*QS_LD + n_load] = v4.y;
                Ks[(4*j+2)*QS_LD + n_load] = v4.z;
                Ks[(4*j+3)*QS_LD + n_load] = v4.w;
                local += v4.x*v4.x + v4.y*v4.y + v4.z*v4.z + v4.w*v4.w;
            }
            ssq4[n_load*4 + j0] = local;   // deterministic (no float atomics)
            if (j0 == 0) impS[n_load] = pimp;
        }
        __syncthreads();

        // --- per-thread scales for its 4 columns (MUFU latency hidden by GEMM)
        float s0, s1, s2, s3;
        {
            const float* sq = ssq4 + (4*tx)*4;
            float ssa = sq[0]  + sq[1]  + sq[2]  + sq[3];
            float ssb = sq[4]  + sq[5]  + sq[6]  + sq[7];
            float ssc = sq[8]  + sq[9]  + sq[10] + sq[11];
            float ssd = sq[12] + sq[13] + sq[14] + sq[15];
            s0 = impS[4*tx+0] / fmaxf(sqrtf(ssa), 1e-12f);
            s1 = impS[4*tx+1] / fmaxf(sqrtf(ssb), 1e-12f);
            s2 = impS[4*tx+2] / fmaxf(sqrtf(ssc), 1e-12f);
            s3 = impS[4*tx+3] / fmaxf(sqrtf(ssd), 1e-12f);
        }

        // --- 64x64 sim tile, 4x4 register blocking, float4 smem reads
        {
            float acc00=0,acc01=0,acc02=0,acc03=0;
            float acc10=0,acc11=0,acc12=0,acc13=0;
            float acc20=0,acc21=0,acc22=0,acc23=0;
            float acc30=0,acc31=0,acc32=0,acc33=0;
            const float* qb = Qs + 4*ty;
            const float* kb = Ks + 4*tx;
            #pragma unroll 4
            for (int d = 0; d < D; d++) {
                float4 qv = *reinterpret_cast<const float4*>(qb + d*QS_LD);
                float4 kv = *reinterpret_cast<const float4*>(kb + d*QS_LD);
                acc00 += qv.x*kv.x; acc01 += qv.x*kv.y; acc02 += qv.x*kv.z; acc03 += qv.x*kv.w;
                acc10 += qv.y*kv.x; acc11 += qv.y*kv.y; acc12 += qv.y*kv.z; acc13 += qv.y*kv.w;
                acc20 += qv.z*kv.x; acc21 += qv.z*kv.y; acc22 += qv.z*kv.z; acc23 += qv.z*kv.w;
                acc30 += qv.w*kv.x; acc31 += qv.w*kv.y; acc32 += qv.w*kv.z; acc33 += qv.w*kv.w;
            }
            float* sr0 = sims + (4*ty+0)*SIM_LD + 4*tx;
            float* sr1 = sims + (4*ty+1)*SIM_LD + 4*tx;
            float* sr2 = sims + (4*ty+2)*SIM_LD + 4*tx;
            float* sr3 = sims + (4*ty+3)*SIM_LD + 4*tx;
            sr0[0]=acc00*s0; sr0[1]=acc01*s1; sr0[2]=acc02*s2; sr0[3]=acc03*s3;
            sr1[0]=acc10*s0; sr1[1]=acc11*s1; sr1[2]=acc12*s2; sr1[3]=acc13*s3;
            sr2[0]=acc20*s0; sr2[1]=acc21*s1; sr2[2]=acc22*s2; sr2[3]=acc23*s3;
            sr3[0]=acc30*s0; sr3[1]=acc31*s1; sr3[2]=acc32*s2; sr3[3]=acc33*s3;
        }

        // --- issue next tile's global loads; latency overlaps scan + next STS
        do_prefetch(t + G2);

        __syncthreads();

        // --- update running top-8 (one thread per batch row)
        if (tid < 64) {
            const float* sr = sims + tid*SIM_LD;
            int nmax = (N - base < TILE) ? (N - base) : TILE;
            for (int n = 0; n < nmax; n++) {
                float v = sr[n];
                if (v > vmin) {
                    tv[minpos] = v; tix[minpos] = base + n;
                    vmin = tv[0]; minpos = 0;
                    #pragma unroll
                    for (int k = 1; k < KTOP; k++)
                        if (tv[k] < vmin) { vmin = tv[k]; minpos = k; }
                }
            }
        }
    }

    if (tid < 64) {
        int o = (tid*G2 + g)*KTOP;
        #pragma unroll
        for (int k = 0; k < KTOP; k++) { g_cval[o+k] = tv[k]; g_cidx[o+k] = tix[k]; }
    }
}

// ---------------------------------------------------------------------------
// Kernel 3: merge candidates -> global top-8, gather values, softmax attention,
// combine, out = mem @ W_comb^T + b_comb
// ---------------------------------------------------------------------------
__global__ void final_kernel(const float* __restrict__ values,
                             const float* __restrict__ w_attn,
                             const float* __restrict__ b_attn,
                             const float* __restrict__ Wcomb,
                             const float* __restrict__ bcomb,
                             float* __restrict__ out) {
    __shared__ float cv[NCAND];
    __shared__ int   ci[NCAND];
    __shared__ float rv[256];
    __shared__ int   rp[256];
    __shared__ int   topidx[KTOP];
    __shared__ float vs[KTOP*129];
    __shared__ float wa[D];
    __shared__ float ts[KTOP];
    __shared__ float sc[KTOP];
    __shared__ float ms[D];

    const int b = blockIdx.x;
    const int tid = threadIdx.x;          // 256 threads

    for (int i = tid; i < NCAND; i += 256) {
        cv[i] = g_cval[b*NCAND + i];
        ci[i] = g_cidx[b*NCAND + i];
    }
    if (tid < D) wa[tid] = w_attn[tid];
    __syncthreads();

    // 8 rounds of block argmax over candidates
    for (int k = 0; k < KTOP; k++) {
        float best = -INFINITY; int bp = 0;
        for (int i = tid; i < NCAND; i += 256)
            if (cv[i] > best) { best = cv[i]; bp = i; }
        rv[tid] = best; rp[tid] = bp;
        __syncthreads();
        for (int s = 128; s > 0; s >>= 1) {
            if (tid < s && rv[tid+s] > rv[tid]) { rv[tid] = rv[tid+s]; rp[tid] = rp[tid+s]; }
            __syncthreads();
        }
        if (tid == 0) { topidx[k] = ci[rp[0]]; cv[rp[0]] = -INFINITY; }
        __syncthreads();
    }

    // gather retrieved values
    if (tid < D) {
        #pragma unroll
        for (int k = 0; k < KTOP; k++)
            vs[k*129 + tid] = values[(size_t)topidx[k]*D + tid];
    }
    __syncthreads();

    // attention logits
    if (tid < KTOP) {
        float acc = b_attn[0];
        for (int d = 0; d < D; d++) acc += vs[tid*129 + d] * wa[d];
        ts[tid] = acc;
    }
    __syncthreads();
    if (tid == 0) {
        float m = ts[0];
        #pragma unroll
        for (int k = 1; k < KTOP; k++) m = fmaxf(m, ts[k]);
        float e[KTOP]; float s = 0.f;
        #pragma unroll
        for (int k = 0; k < KTOP; k++) { e[k] = expf(ts[k] - m); s += e[k]; }
        #pragma unroll
        for (int k = 0; k < KTOP; k++) sc[k] = e[k] / s;
    }
    __syncthreads();

    // weighted memory
    if (tid < D) {
        float m = 0.f;
        #pragma unroll
        for (int k = 0; k < KTOP; k++) m += sc[k] * vs[k*129 + tid];
        ms[tid] = m;
    }
    __syncthreads();

    // out = mem @ W_comb^T + b_comb  (warp-coalesced matvec)
    const int lane = tid & 31, w = tid >> 5;   // 8 warps
    for (int d = w; d < D; d += 8) {
        const float* wr = Wcomb + (size_t)d*D;
        float acc = 0.f;
        #pragma unroll
        for (int j = 0; j < 4; j++) {
            int e = lane + 32*j;
            acc += ms[e] * wr[e];
        }
        acc = warpsum(acc);
        if (lane == 0) out[b*D + d] = acc + bcomb[d];
    }
}

// ---------------------------------------------------------------------------
extern "C" void kernel_launch(void* const* d_in, const int* in_sizes, int n_in,
                              void* d_out, int out_size) {
    const float* query      = (const float*)d_in[0];
    const float* keys       = (const float*)d_in[1];
    const float* values     = (const float*)d_in[2];
    const float* importance = (const float*)d_in[3];
    const float* Wq         = (const float*)d_in[4];
    const float* bq         = (const float*)d_in[5];
    const float* w_attn     = (const float*)d_in[6];
    const float* b_attn     = (const float*)d_in[7];
    const float* Wcomb      = (const float*)d_in[8];
    const float* bcomb      = (const float*)d_in[9];
    const int N = in_sizes[1] / D;

    const size_t smem2_bytes = (size_t)(D*QS_LD*2 + B*SIM_LD + 256 + 64) * sizeof(float);
    cudaFuncSetAttribute(sim_topk_kernel,
                         cudaFuncAttributeMaxDynamicSharedMemorySize, (int)smem2_bytes);

    qproj_kernel<<<256, 256>>>(query, Wq, bq);
    sim_topk_kernel<<<G2, 256, smem2_bytes>>>(keys, importance, N);
    final_kernel<<<B, 256>>>(values, w_attn, b_attn, Wcomb, bcomb, (float*)d_out);
}

// round 5
// speedup vs baseline: 1.1647x; 1.0020x over previous
#include <cuda_runtime.h>
#include <math.h>

#define B 64
#define C 256
#define D 128
#define KTOP 8
#define G2 296
#define TILE 64
#define NCAND (G2*KTOP)
#define QS_LD 68
#define SIM_LD 65

// scratch (device globals: no allocations allowed)
__device__ float g_qT[D*B];               // q (unnormalized) transposed [d][b]
__device__ float g_cval[B*G2*KTOP];       // per-block top-8 values
__device__ int   g_cidx[B*G2*KTOP];       // per-block top-8 indices

__device__ __forceinline__ float warpsum(float v) {
    v += __shfl_xor_sync(0xffffffff, v, 16);
    v += __shfl_xor_sync(0xffffffff, v, 8);
    v += __shfl_xor_sync(0xffffffff, v, 4);
    v += __shfl_xor_sync(0xffffffff, v, 2);
    v += __shfl_xor_sync(0xffffffff, v, 1);
    return v;
}

// ---------------------------------------------------------------------------
// Kernel 1: q = query @ W_q^T + b_q  (NO normalization: 1/||q|| is a positive
// per-row scalar; top-k indices are invariant and sim values are selection-only)
// 2048 warps, each computes 4 outputs with interleaved reductions.
// ---------------------------------------------------------------------------
__global__ void qproj_kernel(const float* __restrict__ query,
                             const float* __restrict__ Wq,
                             const float* __restrict__ bq) {
    const int gw   = (blockIdx.x * blockDim.x + threadIdx.x) >> 5;  // 0..2047
    const int lane = threadIdx.x & 31;
    const int b    = gw >> 5;           // 0..63
    const int d0   = (gw & 31) * 4;     // 0,4,...,124

    const float* qr = query + (size_t)b * C;
    const float* w0 = Wq + (size_t)(d0 + 0) * C;
    const float* w1 = Wq + (size_t)(d0 + 1) * C;
    const float* w2 = Wq + (size_t)(d0 + 2) * C;
    const float* w3 = Wq + (size_t)(d0 + 3) * C;

    float a0 = 0.f, a1 = 0.f, a2 = 0.f, a3 = 0.f;
    #pragma unroll
    for (int j = 0; j < 8; j++) {
        int c = lane + 32 * j;
        float q = __ldg(qr + c);
        a0 += q * __ldg(w0 + c);
        a1 += q * __ldg(w1 + c);
        a2 += q * __ldg(w2 + c);
        a3 += q * __ldg(w3 + c);
    }
    #pragma unroll
    for (int off = 16; off; off >>= 1) {
        a0 += __shfl_xor_sync(0xffffffff, a0, off);
        a1 += __shfl_xor_sync(0xffffffff, a1, off);
        a2 += __shfl_xor_sync(0xffffffff, a2, off);
        a3 += __shfl_xor_sync(0xffffffff, a3, off);
    }
    if (lane == 0) {
        g_qT[(d0 + 0) * B + b] = a0 + bq[d0 + 0];
        g_qT[(d0 + 1) * B + b] = a1 + bq[d0 + 1];
        g_qT[(d0 + 2) * B + b] = a2 + bq[d0 + 2];
        g_qT[(d0 + 3) * B + b] = a3 + bq[d0 + 3];
    }
}

// ---------------------------------------------------------------------------
// Kernel 2: sim tile GEMM + per-block running top-8 per batch row.
// Software-pipelined: next tile prefetched into registers during compute/scan.
// smem: Qs[128][68] | Ks[128][68] | sims[64][65] | ssq4[256] | impS[64]
// ---------------------------------------------------------------------------
__global__ void __launch_bounds__(256, 2)
sim_topk_kernel(const float* __restrict__ keys,
                const float* __restrict__ importance,
                int N) {
    extern __shared__ float smem2[];
    float* Qs   = smem2;
    float* Ks   = Qs + D*QS_LD;
    float* sims = Ks + D*QS_LD;
    float* ssq4 = sims + B*SIM_LD;
    float* impS = ssq4 + 256;

    const int tid = threadIdx.x;          // 256 threads
    const int g   = blockIdx.x;

    // load resident Q (transposed) once
    for (int i = tid; i < D*B; i += 256) {
        int d = i >> 6, bb = i & 63;
        Qs[d*QS_LD + bb] = g_qT[i];
    }

    // running top-8 (threads 0..63 own one batch row each)
    float tv[KTOP]; int tix[KTOP];
    #pragma unroll
    for (int k = 0; k < KTOP; k++) { tv[k] = -INFINITY; tix[k] = 0; }
    float vmin = -INFINITY; int minpos = 0;

    const int T = (N + TILE - 1) / TILE;
    const int ty = tid >> 4, tx = tid & 15;       // 16x16 thread tile
    const int n_load = tid >> 2, j0 = tid & 3;    // 4 threads per key row

    // ---- prefetch helper state (registers)
    float4 pf[8];
    float  pimp = 0.f;

    auto do_prefetch = [&](int t) {
        int gk = t * TILE + n_load;
        bool valid = (t < T) && (gk < N);
        const float4* krow = reinterpret_cast<const float4*>(keys + (size_t)gk * D);
        #pragma unroll
        for (int jj = 0; jj < 8; jj++) {
            int j = j0 + 4*jj;
            pf[jj] = valid ? krow[j] : make_float4(0.f, 0.f, 0.f, 0.f);
        }
        if (j0 == 0) pimp = valid ? importance[gk] : 0.f;
    };

    do_prefetch(g);

    for (int t = g; t < T; t += G2) {
        const int base = t * TILE;
        __syncthreads();   // previous compute finished reading Ks / Qs loaded

        // --- store prefetched tile transposed into Ks[d][n] + partial sum-sq
        {
            float local = 0.f;
            #pragma unroll
            for (int jj = 0; jj < 8; jj++) {
                int j = j0 + 4*jj;
                float4 v4 = pf[jj];
                Ks[(4*j+0)*QS_LD + n_load] = v4.x;
                Ks[(4*j+1)*QS_LD + n_load] = v4.y;
                Ks[(4*j+2)*QS_LD + n_load] = v4.z;
                Ks[(4*j+3)*QS_LD + n_load] = v4.w;
                local += v4.x*v4.x + v4.y*v4.y + v4.z*v4.z + v4.w*v4.w;
            }
            ssq4[n_load*4 + j0] = local;   // deterministic (no float atomics)
            if (j0 == 0) impS[n_load] = pimp;
        }
        __syncthreads();

        // --- per-thread scales for its 4 columns (MUFU latency hidden by GEMM)
        float s0, s1, s2, s3;
        {
            const float* sq = ssq4 + (4*tx)*4;
            float ssa = sq[0]  + sq[1]  + sq[2]  + sq[3];
            float ssb = sq[4]  + sq[5]  + sq[6]  + sq[7];
            float ssc = sq[8]  + sq[9]  + sq[10] + sq[11];
            float ssd = sq[12] + sq[13] + sq[14] + sq[15];
            s0 = impS[4*tx+0] / fmaxf(sqrtf(ssa), 1e-12f);
            s1 = impS[4*tx+1] / fmaxf(sqrtf(ssb), 1e-12f);
            s2 = impS[4*tx+2] / fmaxf(sqrtf(ssc), 1e-12f);
            s3 = impS[4*tx+3] / fmaxf(sqrtf(ssd), 1e-12f);
        }

        // --- 64x64 sim tile, 4x4 register blocking, float4 smem reads
        {
            float acc00=0,acc01=0,acc02=0,acc03=0;
            float acc10=0,acc11=0,acc12=0,acc13=0;
            float acc20=0,acc21=0,acc22=0,acc23=0;
            float acc30=0,acc31=0,acc32=0,acc33=0;
            const float* qb = Qs + 4*ty;
            const float* kb = Ks + 4*tx;
            #pragma unroll 4
            for (int d = 0; d < D; d++) {
                float4 qv = *reinterpret_cast<const float4*>(qb + d*QS_LD);
                float4 kv = *reinterpret_cast<const float4*>(kb + d*QS_LD);
                acc00 += qv.x*kv.x; acc01 += qv.x*kv.y; acc02 += qv.x*kv.z; acc03 += qv.x*kv.w;
                acc10 += qv.y*kv.x; acc11 += qv.y*kv.y; acc12 += qv.y*kv.z; acc13 += qv.y*kv.w;
                acc20 += qv.z*kv.x; acc21 += qv.z*kv.y; acc22 += qv.z*kv.z; acc23 += qv.z*kv.w;
                acc30 += qv.w*kv.x; acc31 += qv.w*kv.y; acc32 += qv.w*kv.z; acc33 += qv.w*kv.w;
            }
            float* sr0 = sims + (4*ty+0)*SIM_LD + 4*tx;
            float* sr1 = sims + (4*ty+1)*SIM_LD + 4*tx;
            float* sr2 = sims + (4*ty+2)*SIM_LD + 4*tx;
            float* sr3 = sims + (4*ty+3)*SIM_LD + 4*tx;
            sr0[0]=acc00*s0; sr0[1]=acc01*s1; sr0[2]=acc02*s2; sr0[3]=acc03*s3;
            sr1[0]=acc10*s0; sr1[1]=acc11*s1; sr1[2]=acc12*s2; sr1[3]=acc13*s3;
            sr2[0]=acc20*s0; sr2[1]=acc21*s1; sr2[2]=acc22*s2; sr2[3]=acc23*s3;
            sr3[0]=acc30*s0; sr3[1]=acc31*s1; sr3[2]=acc32*s2; sr3[3]=acc33*s3;
        }

        // --- issue next tile's global loads; latency overlaps scan + next STS
        do_prefetch(t + G2);

        __syncthreads();

        // --- update running top-8 (one thread per batch row)
        if (tid < 64) {
            const float* sr = sims + tid*SIM_LD;
            int nmax = (N - base < TILE) ? (N - base) : TILE;
            for (int n = 0; n < nmax; n++) {
                float v = sr[n];
                if (v > vmin) {
                    tv[minpos] = v; tix[minpos] = base + n;
                    vmin = tv[0]; minpos = 0;
                    #pragma unroll
                    for (int k = 1; k < KTOP; k++)
                        if (tv[k] < vmin) { vmin = tv[k]; minpos = k; }
                }
            }
        }
    }

    if (tid < 64) {
        int o = (tid*G2 + g)*KTOP;
        #pragma unroll
        for (int k = 0; k < KTOP; k++) { g_cval[o+k] = tv[k]; g_cidx[o+k] = tix[k]; }
    }
}

// ---------------------------------------------------------------------------
// Kernel 3: merge candidates -> global top-8, gather values, softmax attention,
// combine, out = mem @ W_comb^T + b_comb
// ---------------------------------------------------------------------------
__global__ void final_kernel(const float* __restrict__ values,
                             const float* __restrict__ w_attn,
                             const float* __restrict__ b_attn,
                             const float* __restrict__ Wcomb,
                             const float* __restrict__ bcomb,
                             float* __restrict__ out) {
    __shared__ float cv[NCAND];
    __shared__ int   ci[NCAND];
    __shared__ float rv[256];
    __shared__ int   rp[256];
    __shared__ int   topidx[KTOP];
    __shared__ float vs[KTOP*129];
    __shared__ float wa[D];
    __shared__ float ts[KTOP];
    __shared__ float sc[KTOP];
    __shared__ float ms[D];

    const int b = blockIdx.x;
    const int tid = threadIdx.x;          // 256 threads

    for (int i = tid; i < NCAND; i += 256) {
        cv[i] = g_cval[b*NCAND + i];
        ci[i] = g_cidx[b*NCAND + i];
    }
    if (tid < D) wa[tid] = w_attn[tid];
    __syncthreads();

    // 8 rounds of block argmax over candidates
    for (int k = 0; k < KTOP; k++) {
        float best = -INFINITY; int bp = 0;
        for (int i = tid; i < NCAND; i += 256)
            if (cv[i] > best) { best = cv[i]; bp = i; }
        rv[tid] = best; rp[tid] = bp;
        __syncthreads();
        for (int s = 128; s > 0; s >>= 1) {
            if (tid < s && rv[tid+s] > rv[tid]) { rv[tid] = rv[tid+s]; rp[tid] = rp[tid+s]; }
            __syncthreads();
        }
        if (tid == 0) { topidx[k] = ci[rp[0]]; cv[rp[0]] = -INFINITY; }
        __syncthreads();
    }

    // gather retrieved values
    if (tid < D) {
        #pragma unroll
        for (int k = 0; k < KTOP; k++)
            vs[k*129 + tid] = values[(size_t)topidx[k]*D + tid];
    }
    __syncthreads();

    // attention logits
    if (tid < KTOP) {
        float acc = b_attn[0];
        for (int d = 0; d < D; d++) acc += vs[tid*129 + d] * wa[d];
        ts[tid] = acc;
    }
    __syncthreads();
    if (tid == 0) {
        float m = ts[0];
        #pragma unroll
        for (int k = 1; k < KTOP; k++) m = fmaxf(m, ts[k]);
        float e[KTOP]; float s = 0.f;
        #pragma unroll
        for (int k = 0; k < KTOP; k++) { e[k] = expf(ts[k] - m); s += e[k]; }
        #pragma unroll
        for (int k = 0; k < KTOP; k++) sc[k] = e[k] / s;
    }
    __syncthreads();

    // weighted memory
    if (tid < D) {
        float m = 0.f;
        #pragma unroll
        for (int k = 0; k < KTOP; k++) m += sc[k] * vs[k*129 + tid];
        ms[tid] = m;
    }
    __syncthreads();

    // out = mem @ W_comb^T + b_comb  (warp-coalesced matvec)
    const int lane = tid & 31, w = tid >> 5;   // 8 warps
    for (int d = w; d < D; d += 8) {
        const float* wr = Wcomb + (size_t)d*D;
        float acc = 0.f;
        #pragma unroll
        for (int j = 0; j < 4; j++) {
            int e = lane + 32*j;
            acc += ms[e] * wr[e];
        }
        acc = warpsum(acc);
        if (lane == 0) out[b*D + d] = acc + bcomb[d];
    }
}

// ---------------------------------------------------------------------------
extern "C" void kernel_launch(void* const* d_in, const int* in_sizes, int n_in,
                              void* d_out, int out_size) {
    const float* query      = (const float*)d_in[0];
    const float* keys       = (const float*)d_in[1];
    const float* values     = (const float*)d_in[2];
    const float* importance = (const float*)d_in[3];
    const float* Wq         = (const float*)d_in[4];
    const float* bq         = (const float*)d_in[5];
    const float* w_attn     = (const float*)d_in[6];
    const float* b_attn     = (const float*)d_in[7];
    const float* Wcomb      = (const float*)d_in[8];
    const float* bcomb      = (const float*)d_in[9];
    const int N = in_sizes[1] / D;

    const size_t smem2_bytes = (size_t)(D*QS_LD*2 + B*SIM_LD + 256 + 64) * sizeof(float);
    cudaFuncSetAttribute(sim_topk_kernel,
                         cudaFuncAttributeMaxDynamicSharedMemorySize, (int)smem2_bytes);

    qproj_kernel<<<256, 256>>>(query, Wq, bq);
    sim_topk_kernel<<<G2, 256, smem2_bytes>>>(keys, importance, N);
    final_kernel<<<B, 256>>>(values, w_attn, b_attn, Wcomb, bcomb, (float*)d_out);
}

// round 6
// speedup vs baseline: 1.3435x; 1.1535x over previous
#include <cuda_runtime.h>
#include <math.h>

#define B 64
#define C 256
#define D 128
#define KTOP 8
#define G2 296
#define TILE 128
#define NCAND (G2*KTOP)
#define QS_LD 68
#define KS_LD 132

// scratch (device globals: no allocations allowed)
__device__ float g_qT[D*B];               // q (unnormalized) transposed [d][b]
__device__ float g_cval[B*G2*KTOP];       // per-block top-8 values
__device__ int   g_cidx[B*G2*KTOP];       // per-block top-8 indices

__device__ __forceinline__ float warpsum(float v) {
    v += __shfl_xor_sync(0xffffffff, v, 16);
    v += __shfl_xor_sync(0xffffffff, v, 8);
    v += __shfl_xor_sync(0xffffffff, v, 4);
    v += __shfl_xor_sync(0xffffffff, v, 2);
    v += __shfl_xor_sync(0xffffffff, v, 1);
    return v;
}

// packed fp32x2 FMA: acc = a*b + acc  (per-lane IEEE fma on both halves)
#define FMA2(acc, a, b) \
    asm("fma.rn.f32x2 %0, %1, %2, %0;" : "+l"(acc) : "l"(a), "l"(b))

#define PACK2(out, f) \
    asm("mov.b64 %0, {%1, %1};" : "=l"(out) : "r"(__float_as_uint(f)))

__device__ __forceinline__ void unpack2(unsigned long long v, float& lo, float& hi) {
    unsigned int a, b;
    asm("mov.b64 {%0, %1}, %2;" : "=r"(a), "=r"(b) : "l"(v));
    lo = __uint_as_float(a); hi = __uint_as_float(b);
}

// ---------------------------------------------------------------------------
// Kernel 1: q = query @ W_q^T + b_q  (no normalization: positive per-row scale
// is top-k order invariant and sim values are selection-only)
// ---------------------------------------------------------------------------
__global__ void qproj_kernel(const float* __restrict__ query,
                             const float* __restrict__ Wq,
                             const float* __restrict__ bq) {
    const int gw   = (blockIdx.x * blockDim.x + threadIdx.x) >> 5;  // 0..2047
    const int lane = threadIdx.x & 31;
    const int b    = gw >> 5;           // 0..63
    const int d0   = (gw & 31) * 4;     // 0,4,...,124

    const float* qr = query + (size_t)b * C;
    const float* w0 = Wq + (size_t)(d0 + 0) * C;
    const float* w1 = Wq + (size_t)(d0 + 1) * C;
    const float* w2 = Wq + (size_t)(d0 + 2) * C;
    const float* w3 = Wq + (size_t)(d0 + 3) * C;

    float a0 = 0.f, a1 = 0.f, a2 = 0.f, a3 = 0.f;
    #pragma unroll
    for (int j = 0; j < 8; j++) {
        int c = lane + 32 * j;
        float q = __ldg(qr + c);
        a0 += q * __ldg(w0 + c);
        a1 += q * __ldg(w1 + c);
        a2 += q * __ldg(w2 + c);
        a3 += q * __ldg(w3 + c);
    }
    #pragma unroll
    for (int off = 16; off; off >>= 1) {
        a0 += __shfl_xor_sync(0xffffffff, a0, off);
        a1 += __shfl_xor_sync(0xffffffff, a1, off);
        a2 += __shfl_xor_sync(0xffffffff, a2, off);
        a3 += __shfl_xor_sync(0xffffffff, a3, off);
    }
    if (lane == 0) {
        g_qT[(d0 + 0) * B + b] = a0 + bq[d0 + 0];
        g_qT[(d0 + 1) * B + b] = a1 + bq[d0 + 1];
        g_qT[(d0 + 2) * B + b] = a2 + bq[d0 + 2];
        g_qT[(d0 + 3) * B + b] = a3 + bq[d0 + 3];
    }
}

// ---------------------------------------------------------------------------
// Kernel 2: 64x128 sim tile via packed f32x2 FMAs (8x4 thread tile, row-paired
// accumulators), + per-block running top-8 per batch row (4 scanners/row).
// smem: Qs[128][68] | Ks[128][132] (aliased by sims[64][132] + merge buffers)
//       | ssq2[256] | impS[128]
// ---------------------------------------------------------------------------
__global__ void __launch_bounds__(256, 2)
sim_topk_kernel(const float* __restrict__ keys,
                const float* __restrict__ importance,
                int N) {
    extern __shared__ float smem2[];
    float* Qs   = smem2;                       // 128*68   = 8704 floats
    float* Ks   = Qs + D*QS_LD;                // 128*132  = 16896 floats
    float* ssq2 = Ks + D*KS_LD;                // 256
    float* impS = ssq2 + 256;                  // 128
    // aliases into Ks region (sync-separated from GEMM reads):
    float* simsS = Ks;                         // 64*132 = 8448 floats
    float* bufv  = Ks + 8448;                  // 256*8 = 2048 floats
    int*   bufi  = (int*)(Ks + 8448 + 2048);   // 2048 ints

    const int tid = threadIdx.x;               // 256 threads
    const int g   = blockIdx.x;

    // resident Q (transposed [d][b])
    for (int i = tid; i < D*B; i += 256) {
        int d = i >> 6, bb = i & 63;
        Qs[d*QS_LD + bb] = g_qT[i];
    }

    // running top-8 per (row, 32-col slice) stream
    float tv[KTOP]; int tix[KTOP];
    #pragma unroll
    for (int k = 0; k < KTOP; k++) { tv[k] = -INFINITY; tix[k] = 0; }
    float vmin = -INFINITY; int minpos = 0;

    const int T = (N + TILE - 1) / TILE;
    const int ty = tid >> 5, tx = tid & 31;    // GEMM: rows 8ty.., cols 4tx..
    const int n_load = tid >> 1, j0 = tid & 1; // load: 2 threads per key row
    const int rr = tid >> 2, ss = tid & 3;     // scan: 4 threads per row

    for (int t = g; t < T; t += G2) {
        const int base = t * TILE;
        __syncthreads();   // prev scan done reading sims (alias of Ks)

        // --- load 128-key tile transposed into Ks[d][n] + partial sum-squares
        {
            int gk = base + n_load;
            bool valid = gk < N;
            const float4* krow = reinterpret_cast<const float4*>(keys + (size_t)gk * D);
            float local = 0.f;
            #pragma unroll
            for (int m = 0; m < 16; m++) {
                int j = j0 + 2*m;
                float4 v4 = valid ? krow[j] : make_float4(0.f,0.f,0.f,0.f);
                Ks[(4*j+0)*KS_LD + n_load] = v4.x;
                Ks[(4*j+1)*KS_LD + n_load] = v4.y;
                Ks[(4*j+2)*KS_LD + n_load] = v4.z;
                Ks[(4*j+3)*KS_LD + n_load] = v4.w;
                local += v4.x*v4.x + v4.y*v4.y + v4.z*v4.z + v4.w*v4.w;
            }
            ssq2[n_load*2 + j0] = local;       // deterministic (no float atomics)
            if (j0 == 0) impS[n_load] = valid ? importance[gk] : 0.f;
        }
        __syncthreads();

        // --- per-thread scales for its 4 cols (MUFU hidden under GEMM)
        float s0, s1, s2, s3;
        {
            int c = 4*tx;
            s0 = impS[c+0] / fmaxf(sqrtf(ssq2[2*(c+0)] + ssq2[2*(c+0)+1]), 1e-12f);
            s1 = impS[c+1] / fmaxf(sqrtf(ssq2[2*(c+1)] + ssq2[2*(c+1)+1]), 1e-12f);
            s2 = impS[c+2] / fmaxf(sqrtf(ssq2[2*(c+2)] + ssq2[2*(c+2)+1]), 1e-12f);
            s3 = impS[c+3] / fmaxf(sqrtf(ssq2[2*(c+3)] + ssq2[2*(c+3)+1]), 1e-12f);
        }

        // --- GEMM: 8x4 per thread, f32x2 packed FMAs (row pairs)
        unsigned long long acc[4][4];
        #pragma unroll
        for (int p = 0; p < 4; p++)
            #pragma unroll
            for (int j = 0; j < 4; j++) acc[p][j] = 0ULL;
        {
            const float* qb = Qs + 8*ty;
            const float* kb = Ks + 4*tx;
            #pragma unroll 4
            for (int d = 0; d < D; d++) {
                float4 k4 = *reinterpret_cast<const float4*>(kb + d*KS_LD);
                ulonglong2 qA = *reinterpret_cast<const ulonglong2*>(qb + d*QS_LD);
                ulonglong2 qB = *reinterpret_cast<const ulonglong2*>(qb + d*QS_LD + 4);
                unsigned long long kk0, kk1, kk2, kk3;
                PACK2(kk0, k4.x); PACK2(kk1, k4.y);
                PACK2(kk2, k4.z); PACK2(kk3, k4.w);
                FMA2(acc[0][0], qA.x, kk0); FMA2(acc[0][1], qA.x, kk1);
                FMA2(acc[0][2], qA.x, kk2); FMA2(acc[0][3], qA.x, kk3);
                FMA2(acc[1][0], qA.y, kk0); FMA2(acc[1][1], qA.y, kk1);
                FMA2(acc[1][2], qA.y, kk2); FMA2(acc[1][3], qA.y, kk3);
                FMA2(acc[2][0], qB.x, kk0); FMA2(acc[2][1], qB.x, kk1);
                FMA2(acc[2][2], qB.x, kk2); FMA2(acc[2][3], qB.x, kk3);
                FMA2(acc[3][0], qB.y, kk0); FMA2(acc[3][1], qB.y, kk1);
                FMA2(acc[3][2], qB.y, kk2); FMA2(acc[3][3], qB.y, kk3);
            }
        }
        __syncthreads();   // all GEMM reads of Ks done before sims overwrite

        // --- scaled sims to smem (rows 8ty+2p / 8ty+2p+1, cols 4tx..)
        #pragma unroll
        for (int p = 0; p < 4; p++) {
            float l0,h0,l1,h1,l2,h2,l3,h3;
            unpack2(acc[p][0], l0, h0); unpack2(acc[p][1], l1, h1);
            unpack2(acc[p][2], l2, h2); unpack2(acc[p][3], l3, h3);
            int r0 = 8*ty + 2*p;
            float4 v0 = make_float4(l0*s0, l1*s1, l2*s2, l3*s3);
            float4 v1 = make_float4(h0*s0, h1*s1, h2*s2, h3*s3);
            *reinterpret_cast<float4*>(simsS + r0*KS_LD + 4*tx)       = v0;
            *reinterpret_cast<float4*>(simsS + (r0+1)*KS_LD + 4*tx)   = v1;
        }
        __syncthreads();

        // --- running top-8 update: 4 scanners per row, 32 values each
        {
            int cbase = base + 32*ss;
            int avail = N - cbase;
            int cnt = avail < 32 ? (avail < 0 ? 0 : avail) : 32;
            const float* sr = simsS + rr*KS_LD + 32*ss;
            for (int n = 0; n < cnt; n++) {
                float v = sr[n];
                if (v > vmin) {
                    tv[minpos] = v; tix[minpos] = cbase + n;
                    vmin = tv[0]; minpos = 0;
                    #pragma unroll
                    for (int k = 1; k < KTOP; k++)
                        if (tv[k] < vmin) { vmin = tv[k]; minpos = k; }
                }
            }
        }
    }

    // --- merge 4 scanner streams per row -> 8 candidates per row
    __syncthreads();
    #pragma unroll
    for (int k = 0; k < KTOP; k++) { bufv[tid*KTOP + k] = tv[k]; bufi[tid*KTOP + k] = tix[k]; }
    __syncthreads();
    if (tid < 64) {
        float fv[KTOP]; int fi[KTOP];
        #pragma unroll
        for (int k = 0; k < KTOP; k++) { fv[k] = -INFINITY; fi[k] = 0; }
        float fmin = -INFINITY; int fpos = 0;
        int e0 = (4*tid)*KTOP;
        for (int e = 0; e < 4*KTOP; e++) {
            float v = bufv[e0 + e];
            if (v > fmin) {
                fv[fpos] = v; fi[fpos] = bufi[e0 + e];
                fmin = fv[0]; fpos = 0;
                #pragma unroll
                for (int k = 1; k < KTOP; k++)
                    if (fv[k] < fmin) { fmin = fv[k]; fpos = k; }
            }
        }
        int o = (tid*G2 + g)*KTOP;
        #pragma unroll
        for (int k = 0; k < KTOP; k++) { g_cval[o+k] = fv[k]; g_cidx[o+k] = fi[k]; }
    }
}

// ---------------------------------------------------------------------------
// Kernel 3: merge candidates -> global top-8, gather values, softmax attention,
// combine, out = mem @ W_comb^T + b_comb
// ---------------------------------------------------------------------------
__global__ void final_kernel(const float* __restrict__ values,
                             const float* __restrict__ w_attn,
                             const float* __restrict__ b_attn,
                             const float* __restrict__ Wcomb,
                             const float* __restrict__ bcomb,
                             float* __restrict__ out) {
    __shared__ float cv[NCAND];
    __shared__ int   ci[NCAND];
    __shared__ float rv[256];
    __shared__ int   rp[256];
    __shared__ int   topidx[KTOP];
    __shared__ float vs[KTOP*129];
    __shared__ float wa[D];
    __shared__ float ts[KTOP];
    __shared__ float sc[KTOP];
    __shared__ float ms[D];

    const int b = blockIdx.x;
    const int tid = threadIdx.x;          // 256 threads

    for (int i = tid; i < NCAND; i += 256) {
        cv[i] = g_cval[b*NCAND + i];
        ci[i] = g_cidx[b*NCAND + i];
    }
    if (tid < D) wa[tid] = w_attn[tid];
    __syncthreads();

    // 8 rounds of block argmax over candidates
    for (int k = 0; k < KTOP; k++) {
        float best = -INFINITY; int bp = 0;
        for (int i = tid; i < NCAND; i += 256)
            if (cv[i] > best) { best = cv[i]; bp = i; }
        rv[tid] = best; rp[tid] = bp;
        __syncthreads();
        for (int s = 128; s > 0; s >>= 1) {
            if (tid < s && rv[tid+s] > rv[tid]) { rv[tid] = rv[tid+s]; rp[tid] = rp[tid+s]; }
            __syncthreads();
        }
        if (tid == 0) { topidx[k] = ci[rp[0]]; cv[rp[0]] = -INFINITY; }
        __syncthreads();
    }

    // gather retrieved values
    if (tid < D) {
        #pragma unroll
        for (int k = 0; k < KTOP; k++)
            vs[k*129 + tid] = values[(size_t)topidx[k]*D + tid];
    }
    __syncthreads();

    // attention logits
    if (tid < KTOP) {
        float acc = b_attn[0];
        for (int d = 0; d < D; d++) acc += vs[tid*129 + d] * wa[d];
        ts[tid] = acc;
    }
    __syncthreads();
    if (tid == 0) {
        float m = ts[0];
        #pragma unroll
        for (int k = 1; k < KTOP; k++) m = fmaxf(m, ts[k]);
        float e[KTOP]; float s = 0.f;
        #pragma unroll
        for (int k = 0; k < KTOP; k++) { e[k] = expf(ts[k] - m); s += e[k]; }
        #pragma unroll
        for (int k = 0; k < KTOP; k++) sc[k] = e[k] / s;
    }
    __syncthreads();

    // weighted memory
    if (tid < D) {
        float m = 0.f;
        #pragma unroll
        for (int k = 0; k < KTOP; k++) m += sc[k] * vs[k*129 + tid];
        ms[tid] = m;
    }
    __syncthreads();

    // out = mem @ W_comb^T + b_comb  (warp-coalesced matvec)
    const int lane = tid & 31, w = tid >> 5;   // 8 warps
    for (int d = w; d < D; d += 8) {
        const float* wr = Wcomb + (size_t)d*D;
        float acc = 0.f;
        #pragma unroll
        for (int j = 0; j < 4; j++) {
            int e = lane + 32*j;
            acc += ms[e] * wr[e];
        }
        acc = warpsum(acc);
        if (lane == 0) out[b*D + d] = acc + bcomb[d];
    }
}

// ---------------------------------------------------------------------------
extern "C" void kernel_launch(void* const* d_in, const int* in_sizes, int n_in,
                              void* d_out, int out_size) {
    const float* query      = (const float*)d_in[0];
    const float* keys       = (const float*)d_in[1];
    const float* values     = (const float*)d_in[2];
    const float* importance = (const float*)d_in[3];
    const float* Wq         = (const float*)d_in[4];
    const float* bq         = (const float*)d_in[5];
    const float* w_attn     = (const float*)d_in[6];
    const float* b_attn     = (const float*)d_in[7];
    const float* Wcomb      = (const float*)d_in[8];
    const float* bcomb      = (const float*)d_in[9];
    const int N = in_sizes[1] / D;

    const size_t smem2_bytes = (size_t)(D*QS_LD + D*KS_LD + 256 + 128) * sizeof(float);
    cudaFuncSetAttribute(sim_topk_kernel,
                         cudaFuncAttributeMaxDynamicSharedMemorySize, (int)smem2_bytes);

    qproj_kernel<<<256, 256>>>(query, Wq, bq);
    sim_topk_kernel<<<G2, 256, smem2_bytes>>>(keys, importance, N);
    final_kernel<<<B, 256>>>(values, w_attn, b_attn, Wcomb, bcomb, (float*)d_out);
}